// round 8
// baseline (speedup 1.0000x reference)
#include <cuda_runtime.h>
#include <cuda_bf16.h>
#include <cstdint>

// ============================================================================
// NT-Xent loss, GB300 (sm_103a) -- HMMA symmetric-Gram.
// R8: 64KB CTAs (A 32K + 2x16K B half-buffers) -> 3 CTAs/SM for phase
// staggering; tiles processed as two 128x64 halves; sqrt(2log2e) prescale;
// finalize inlined into gram tail (last-CTA pattern).
// ============================================================================

#define N_TOTAL 8192
#define HALF    4096
#define DIM     128
#define INV_LOG2E  0.6931471805599453f
#define SQRT_T     1.6986435838080746f   // sqrt(2*log2(e))

#define GRID_GRAM 444                    // 148 SMs * 3 CTAs

__device__ __nv_bfloat16 g_znb[N_TOTAL * DIM];   // rows scaled by SQRT_T
__device__ float g_rowsum[N_TOTAL];
__device__ float g_pos[N_TOTAL];                 // 2log2e * dot units
__device__ float g_exc[N_TOTAL];                 // 2log2e * dot units
__device__ unsigned int g_cnt;

__device__ __forceinline__ uint32_t smem_to_u32(const void* p) {
    uint32_t a;
    asm("{ .reg .u64 t; cvta.to.shared.u64 t, %1; cvt.u32.u64 %0, t; }"
        : "=r"(a) : "l"(p));
    return a;
}
__device__ __forceinline__ float ex2_approx(float x) {
    float y;
    asm("ex2.approx.f32 %0, %1;" : "=f"(y) : "f"(x));
    return y;
}

// ============================================================================
// Kernel 1: normalize rows -> bf16 scaled by SQRT_T (one warp per row)
// ============================================================================
__global__ void normalize_kernel(const float* __restrict__ zi,
                                 const float* __restrict__ zj) {
    int row  = blockIdx.x * 8 + (threadIdx.x >> 5);
    int lane = threadIdx.x & 31;
    const float* src = (row < HALF) ? (zi + (size_t)row * DIM)
                                    : (zj + (size_t)(row - HALF) * DIM);
    float4 v = reinterpret_cast<const float4*>(src)[lane];
    float ss = v.x * v.x + v.y * v.y + v.z * v.z + v.w * v.w;
    #pragma unroll
    for (int o = 16; o; o >>= 1) ss += __shfl_xor_sync(0xFFFFFFFFu, ss, o);
    float inv = SQRT_T / fmaxf(sqrtf(ss), 1e-8f);
    __nv_bfloat162* dst =
        reinterpret_cast<__nv_bfloat162*>(g_znb + (size_t)row * DIM + lane * 4);
    dst[0] = __floats2bfloat162_rn(v.x * inv, v.y * inv);
    dst[1] = __floats2bfloat162_rn(v.z * inv, v.w * inv);
    if (lane == 0) g_rowsum[row] = 0.0f;
    if (row == 0 && lane == 0) g_cnt = 0u;
}

// ============================================================================
// Kernel 2: persistent symmetric Gram GEMM, 128x64 half-tiles, 3 CTAs/SM
// smem: A 32KB | Bh0 16KB | Bh1 16KB   = 64KB
// ============================================================================
#define SMEM_A   0
#define SMEM_B0  32768
#define SMEM_TOT 65536

__device__ __forceinline__ uint32_t tile_off(int row, int chunk16) {
    return (uint32_t)(row * 256 + ((chunk16 ^ (row & 7)) << 4));
}

__device__ __forceinline__ void load_a_async(uint32_t sdst, int row0, int tid) {
    const uint4* gp = reinterpret_cast<const uint4*>(g_znb + (size_t)row0 * DIM);
    #pragma unroll
    for (int it = 0; it < 8; it++) {
        int idx = tid + it * 256;
        int row = idx >> 4, ch = idx & 15;
        asm volatile("cp.async.cg.shared.global [%0], [%1], 16;"
            :: "r"(sdst + tile_off(row, ch)), "l"(gp + (row << 4) + ch));
    }
}
__device__ __forceinline__ void load_b_async(uint32_t sdst, int row0, int tid) {
    const uint4* gp = reinterpret_cast<const uint4*>(g_znb + (size_t)row0 * DIM);
    #pragma unroll
    for (int it = 0; it < 4; it++) {
        int idx = tid + it * 256;
        int row = idx >> 4, ch = idx & 15;
        asm volatile("cp.async.cg.shared.global [%0], [%1], 16;"
            :: "r"(sdst + tile_off(row, ch)), "l"(gp + (row << 4) + ch));
    }
}
#define CP_COMMIT() asm volatile("cp.async.commit_group;" ::: "memory")
#define CP_WAIT0()  asm volatile("cp.async.wait_group 0;"  ::: "memory")

__global__ void __launch_bounds__(256, 3)
gram_kernel(float* __restrict__ out) {
    extern __shared__ char smem[];
    uint32_t sb = smem_to_u32(smem);
    const int tid  = threadIdx.x;
    const int wid  = tid >> 5;
    const int lane = tid & 31;
    const int bid  = blockIdx.x;

    // 2080 tiles over 444 CTAs: first 304 get 5, rest 4
    const int start = bid * 4 + (bid < 304 ? bid : 304);
    const int count = 4 + (bid < 304 ? 1 : 0);

    int mi = 0, rem = start, len = 64;
    while (rem >= len) { rem -= len; len--; mi++; }
    int ni = mi + rem;
    int h = 0;

    const int wm = (wid & 3) * 32;     // 4 m-strips of 32
    const int wn = (wid >> 2) * 32;    // 2 n-strips of 32 (within 64-half)
    const int l7 = lane & 7;
    const int g  = lane >> 3;

    load_a_async(sb + SMEM_A, mi << 7, tid);
    load_b_async(sb + SMEM_B0, (ni << 7), tid);
    CP_COMMIT();
    CP_WAIT0();
    __syncthreads();
    int cur = 0;

    const int total = count * 2;
    for (int s = 0; s < total; s++) {
        const int m0 = mi << 7, n0 = ni << 7;
        const bool diag = (mi == ni);
        const bool last = (s == total - 1);

        // next half-step indices
        int mi_n = mi, ni_n = ni, h_n = 1;
        if (h == 1) {
            h_n = 0; ni_n = ni + 1;
            if (ni_n == 64) { mi_n = mi + 1; ni_n = mi_n; }
        }
        const bool pf = !last && (mi_n == mi);
        if (pf) {
            load_b_async(sb + SMEM_B0 + ((1 - cur) << 14),
                         (ni_n << 7) + (h_n << 6), tid);
            CP_COMMIT();
        }
        const uint32_t bbase = sb + SMEM_B0 + (cur << 14);

        // ---- MMA mainloop: CTA tile 128 x 64, warp tile 32 x 32 ----
        float c[2][4][4];
        #pragma unroll
        for (int mt = 0; mt < 2; mt++)
            #pragma unroll
            for (int nt = 0; nt < 4; nt++)
                #pragma unroll
                for (int q = 0; q < 4; q++) c[mt][nt][q] = 0.0f;

        #pragma unroll
        for (int ks = 0; ks < 8; ks++) {
            uint32_t a[2][4];
            #pragma unroll
            for (int mt = 0; mt < 2; mt++) {
                int row = wm + mt * 16 + l7 + ((g & 1) << 3);
                uint32_t addr = sb + SMEM_A + tile_off(row, ks * 2 + (g >> 1));
                asm volatile(
                    "ldmatrix.sync.aligned.m8n8.x4.shared.b16 {%0,%1,%2,%3}, [%4];"
                    : "=r"(a[mt][0]), "=r"(a[mt][1]), "=r"(a[mt][2]), "=r"(a[mt][3])
                    : "r"(addr));
            }
            uint32_t b[4][2];
            #pragma unroll
            for (int nt2 = 0; nt2 < 2; nt2++) {
                int row = wn + nt2 * 16 + l7 + ((g >> 1) << 3);
                uint32_t addr = bbase + tile_off(row, ks * 2 + (g & 1));
                asm volatile(
                    "ldmatrix.sync.aligned.m8n8.x4.shared.b16 {%0,%1,%2,%3}, [%4];"
                    : "=r"(b[nt2 * 2][0]),     "=r"(b[nt2 * 2][1]),
                      "=r"(b[nt2 * 2 + 1][0]), "=r"(b[nt2 * 2 + 1][1])
                    : "r"(addr));
            }
            #pragma unroll
            for (int mt = 0; mt < 2; mt++)
                #pragma unroll
                for (int nt = 0; nt < 4; nt++)
                    asm volatile(
                        "mma.sync.aligned.m16n8k16.row.col.f32.bf16.bf16.f32 "
                        "{%0,%1,%2,%3}, {%4,%5,%6,%7}, {%8,%9}, {%0,%1,%2,%3};"
                        : "+f"(c[mt][nt][0]), "+f"(c[mt][nt][1]),
                          "+f"(c[mt][nt][2]), "+f"(c[mt][nt][3])
                        : "r"(a[mt][0]), "r"(a[mt][1]), "r"(a[mt][2]), "r"(a[mt][3]),
                          "r"(b[nt][0]), "r"(b[nt][1]));
        }

        // ---- pos / exc extraction (c_loc is tile-local incl. half offset) ----
        if (diag) {
            #pragma unroll
            for (int mt = 0; mt < 2; mt++)
                #pragma unroll
                for (int nt = 0; nt < 4; nt++)
                    #pragma unroll
                    for (int q = 0; q < 4; q++) {
                        int r_loc = wm + mt * 16 + (lane >> 2) + ((q & 2) << 2);
                        int c_loc = h * 64 + wn + nt * 8 + ((lane & 3) << 1) + (q & 1);
                        if (r_loc == c_loc)
                            g_pos[m0 + r_loc] = c[mt][nt][q];
                    }
        } else if (ni - mi == (HALF >> 7)) {
            #pragma unroll
            for (int mt = 0; mt < 2; mt++)
                #pragma unroll
                for (int nt = 0; nt < 4; nt++)
                    #pragma unroll
                    for (int q = 0; q < 4; q++) {
                        int r_loc = wm + mt * 16 + (lane >> 2) + ((q & 2) << 2);
                        int c_loc = h * 64 + wn + nt * 8 + ((lane & 3) << 1) + (q & 1);
                        if (r_loc == c_loc) {
                            float v = c[mt][nt][q];
                            g_exc[m0 + r_loc] = v;
                            g_exc[n0 + r_loc] = v;
                        }
                    }
        }

        // ---- epilogue: bare ex2; row sums + col sums ----
        float cs0[4], cs1[4];
        #pragma unroll
        for (int nt = 0; nt < 4; nt++) { cs0[nt] = 0.0f; cs1[nt] = 0.0f; }

        #pragma unroll
        for (int mt = 0; mt < 2; mt++) {
            float s0 = 0.0f, s1 = 0.0f;
            #pragma unroll
            for (int nt = 0; nt < 4; nt++) {
                float e0 = ex2_approx(c[mt][nt][0]);
                float e1 = ex2_approx(c[mt][nt][1]);
                float e2 = ex2_approx(c[mt][nt][2]);
                float e3 = ex2_approx(c[mt][nt][3]);
                s0 += e0 + e1;
                s1 += e2 + e3;
                cs0[nt] += e0 + e2;
                cs1[nt] += e1 + e3;
            }
            s0 += __shfl_xor_sync(0xFFFFFFFFu, s0, 1);
            s0 += __shfl_xor_sync(0xFFFFFFFFu, s0, 2);
            s1 += __shfl_xor_sync(0xFFFFFFFFu, s1, 1);
            s1 += __shfl_xor_sync(0xFFFFFFFFu, s1, 2);
            if ((lane & 3) == 0) {
                int r = m0 + wm + mt * 16 + (lane >> 2);
                atomicAdd(&g_rowsum[r],     s0);
                atomicAdd(&g_rowsum[r + 8], s1);
            }
        }

        if (!diag) {
            #pragma unroll
            for (int nt = 0; nt < 4; nt++) {
                float u = cs0[nt], v = cs1[nt];
                u += __shfl_xor_sync(0xFFFFFFFFu, u, 4);
                u += __shfl_xor_sync(0xFFFFFFFFu, u, 8);
                u += __shfl_xor_sync(0xFFFFFFFFu, u, 16);
                v += __shfl_xor_sync(0xFFFFFFFFu, v, 4);
                v += __shfl_xor_sync(0xFFFFFFFFu, v, 8);
                v += __shfl_xor_sync(0xFFFFFFFFu, v, 16);
                if (lane < 4) {
                    int cix = n0 + h * 64 + wn + nt * 8 + (lane << 1);
                    atomicAdd(&g_rowsum[cix],     u);
                    atomicAdd(&g_rowsum[cix + 1], v);
                }
            }
        }

        // ---- advance pipeline ----
        if (!last) {
            if (pf) {
                CP_WAIT0();
                __syncthreads();
                cur ^= 1;
            } else {
                __syncthreads();
                load_a_async(sb + SMEM_A, mi_n << 7, tid);
                load_b_async(sb + SMEM_B0 + (cur << 14),
                             (ni_n << 7) + (h_n << 6), tid);
                CP_COMMIT();
                CP_WAIT0();
                __syncthreads();
            }
            mi = mi_n; ni = ni_n; h = h_n;
        }
    }

    // ======================= inline finalize (last CTA) =====================
    __syncthreads();
    __threadfence();
    __shared__ unsigned s_rank;
    if (tid == 0) s_rank = atomicAdd(&g_cnt, 1u);
    __syncthreads();
    if (s_rank == GRID_GRAM - 1) {
        float* red = reinterpret_cast<float*>(smem);
        float acc = 0.0f;
        for (int r = tid; r < N_TOTAL; r += 256) {
            float S = __ldcg(&g_rowsum[r]) - ex2_approx(__ldcg(&g_exc[r]));
            acc += logf(S) - __ldcg(&g_pos[r]) * INV_LOG2E;
        }
        red[tid] = acc;
        __syncthreads();
        #pragma unroll
        for (int st = 128; st > 0; st >>= 1) {
            if (tid < st) red[tid] += red[tid + st];
            __syncthreads();
        }
        if (tid == 0) out[0] = red[0] / (float)N_TOTAL;
    }
}

// ============================================================================
// launch
// ============================================================================
extern "C" void kernel_launch(void* const* d_in, const int* in_sizes, int n_in,
                              void* d_out, int out_size) {
    (void)in_sizes; (void)n_in; (void)out_size;
    const float* zi = (const float*)d_in[0];
    const float* zj = (const float*)d_in[1];
    float* out = (float*)d_out;

    normalize_kernel<<<N_TOTAL / 8, 256>>>(zi, zj);

    cudaFuncSetAttribute(gram_kernel,
                         cudaFuncAttributeMaxDynamicSharedMemorySize, SMEM_TOT);
    gram_kernel<<<GRID_GRAM, 256, SMEM_TOT>>>(out);
}

// round 9
// speedup vs baseline: 1.0099x; 1.0099x over previous
#include <cuda_runtime.h>
#include <cuda_bf16.h>
#include <cstdint>

// ============================================================================
// NT-Xent loss, GB300 (sm_103a) -- HMMA symmetric-Gram, persistent CTAs
// (exact R4 structure: 128x128 tiles, 8 warps, 2 CTAs/SM, dbl-buffered B)
// R9 deltas: sqrt(2log2e) row prescale (bare-ex2 epilogue), 4-row MLP
// normalize, finalize inlined into gram tail.
// ============================================================================

#define N_TOTAL 8192
#define HALF    4096
#define DIM     128
#define INV_LOG2E  0.6931471805599453f
#define SQRT_T     1.6986435838080746f   // sqrt(2*log2(e))

#define GRID_GRAM 296

__device__ __nv_bfloat16 g_znb[N_TOTAL * DIM];   // rows scaled by SQRT_T
__device__ float g_rowsum[N_TOTAL];
__device__ float g_pos[N_TOTAL];                 // 2log2e * dot units
__device__ float g_exc[N_TOTAL];                 // 2log2e * dot units
__device__ unsigned int g_cnt;

__device__ __forceinline__ uint32_t smem_to_u32(const void* p) {
    uint32_t a;
    asm("{ .reg .u64 t; cvta.to.shared.u64 t, %1; cvt.u32.u64 %0, t; }"
        : "=r"(a) : "l"(p));
    return a;
}
__device__ __forceinline__ float ex2_approx(float x) {
    float y;
    asm("ex2.approx.f32 %0, %1;" : "=f"(y) : "f"(x));
    return y;
}

// ============================================================================
// Kernel 1: normalize -> bf16 * SQRT_T. 4 rows per warp, loads front-batched.
// ============================================================================
__global__ void normalize_kernel(const float* __restrict__ zi,
                                 const float* __restrict__ zj) {
    int gw   = blockIdx.x * 8 + (threadIdx.x >> 5);   // 0..2047
    int lane = threadIdx.x & 31;
    int base = gw * 4;

    float4 v[4];
    #pragma unroll
    for (int k = 0; k < 4; k++) {
        int row = base + k;
        const float* src = (row < HALF) ? (zi + (size_t)row * DIM)
                                        : (zj + (size_t)(row - HALF) * DIM);
        v[k] = reinterpret_cast<const float4*>(src)[lane];
    }
    float ss[4];
    #pragma unroll
    for (int k = 0; k < 4; k++)
        ss[k] = v[k].x * v[k].x + v[k].y * v[k].y + v[k].z * v[k].z + v[k].w * v[k].w;
    #pragma unroll
    for (int o = 16; o; o >>= 1) {
        #pragma unroll
        for (int k = 0; k < 4; k++)
            ss[k] += __shfl_xor_sync(0xFFFFFFFFu, ss[k], o);
    }
    #pragma unroll
    for (int k = 0; k < 4; k++) {
        int row = base + k;
        float inv = SQRT_T / fmaxf(sqrtf(ss[k]), 1e-8f);
        __nv_bfloat162* dst =
            reinterpret_cast<__nv_bfloat162*>(g_znb + (size_t)row * DIM + lane * 4);
        dst[0] = __floats2bfloat162_rn(v[k].x * inv, v[k].y * inv);
        dst[1] = __floats2bfloat162_rn(v[k].z * inv, v[k].w * inv);
        if (lane == 0) g_rowsum[row] = 0.0f;
    }
    if (gw == 0 && lane == 0) g_cnt = 0u;
}

// ============================================================================
// Kernel 2: persistent symmetric Gram GEMM (R4 structure) + inline finalize
// smem: A 32KB | B0 32KB | B1 32KB
// ============================================================================
#define SMEM_A   0
#define SMEM_B0  32768
#define SMEM_TOT 98304

__device__ __forceinline__ uint32_t tile_off(int row, int chunk16) {
    return (uint32_t)(row * 256 + ((chunk16 ^ (row & 7)) << 4));
}

__device__ __forceinline__ void load_tile_async(uint32_t sdst, int row0, int tid) {
    const uint4* gp = reinterpret_cast<const uint4*>(g_znb + (size_t)row0 * DIM);
    #pragma unroll
    for (int it = 0; it < 8; it++) {
        int idx = tid + it * 256;
        int row = idx >> 4, ch = idx & 15;
        asm volatile("cp.async.cg.shared.global [%0], [%1], 16;"
            :: "r"(sdst + tile_off(row, ch)), "l"(gp + (row << 4) + ch));
    }
}
#define CP_COMMIT() asm volatile("cp.async.commit_group;" ::: "memory")
#define CP_WAIT0()  asm volatile("cp.async.wait_group 0;"  ::: "memory")

__global__ void __launch_bounds__(256, 2)
gram_kernel(float* __restrict__ out) {
    extern __shared__ char smem[];
    uint32_t sb = smem_to_u32(smem);
    const int tid  = threadIdx.x;
    const int wid  = tid >> 5;
    const int lane = tid & 31;
    const int bid  = blockIdx.x;

    const int start = bid * 7 + (bid < 8 ? bid : 8);
    const int count = (bid < 8) ? 8 : 7;

    int mi = 0, rem = start, len = 64;
    while (rem >= len) { rem -= len; len--; mi++; }
    int ni = mi + rem;

    const int wm = (wid & 3) * 32;
    const int wn = (wid >> 2) * 64;
    const int l7 = lane & 7;
    const int g  = lane >> 3;

    load_tile_async(sb + SMEM_A, mi << 7, tid);
    load_tile_async(sb + SMEM_B0, ni << 7, tid);
    CP_COMMIT();
    CP_WAIT0();
    __syncthreads();
    int cur = 0;

    for (int i = 0; i < count; i++) {
        const int m0 = mi << 7, n0 = ni << 7;
        const bool diag = (mi == ni);
        const bool last = (i == count - 1);
        int mi_n = mi, ni_n = ni + 1;
        if (ni_n == 64) { mi_n = mi + 1; ni_n = mi_n; }
        const bool pf = !last && (mi_n == mi);
        if (pf) {
            load_tile_async(sb + SMEM_B0 + ((1 - cur) << 15), ni_n << 7, tid);
            CP_COMMIT();
        }
        const uint32_t bbase = sb + SMEM_B0 + (cur << 15);

        // ---- MMA mainloop ----
        float c[2][8][4];
        #pragma unroll
        for (int mt = 0; mt < 2; mt++)
            #pragma unroll
            for (int nt = 0; nt < 8; nt++)
                #pragma unroll
                for (int q = 0; q < 4; q++) c[mt][nt][q] = 0.0f;

        #pragma unroll
        for (int ks = 0; ks < 8; ks++) {
            uint32_t a[2][4];
            #pragma unroll
            for (int mt = 0; mt < 2; mt++) {
                int row = wm + mt * 16 + l7 + ((g & 1) << 3);
                uint32_t addr = sb + SMEM_A + tile_off(row, ks * 2 + (g >> 1));
                asm volatile(
                    "ldmatrix.sync.aligned.m8n8.x4.shared.b16 {%0,%1,%2,%3}, [%4];"
                    : "=r"(a[mt][0]), "=r"(a[mt][1]), "=r"(a[mt][2]), "=r"(a[mt][3])
                    : "r"(addr));
            }
            uint32_t b[8][2];
            #pragma unroll
            for (int nt2 = 0; nt2 < 4; nt2++) {
                int row = wn + nt2 * 16 + l7 + ((g >> 1) << 3);
                uint32_t addr = bbase + tile_off(row, ks * 2 + (g & 1));
                asm volatile(
                    "ldmatrix.sync.aligned.m8n8.x4.shared.b16 {%0,%1,%2,%3}, [%4];"
                    : "=r"(b[nt2 * 2][0]),     "=r"(b[nt2 * 2][1]),
                      "=r"(b[nt2 * 2 + 1][0]), "=r"(b[nt2 * 2 + 1][1])
                    : "r"(addr));
            }
            #pragma unroll
            for (int mt = 0; mt < 2; mt++)
                #pragma unroll
                for (int nt = 0; nt < 8; nt++)
                    asm volatile(
                        "mma.sync.aligned.m16n8k16.row.col.f32.bf16.bf16.f32 "
                        "{%0,%1,%2,%3}, {%4,%5,%6,%7}, {%8,%9}, {%0,%1,%2,%3};"
                        : "+f"(c[mt][nt][0]), "+f"(c[mt][nt][1]),
                          "+f"(c[mt][nt][2]), "+f"(c[mt][nt][3])
                        : "r"(a[mt][0]), "r"(a[mt][1]), "r"(a[mt][2]), "r"(a[mt][3]),
                          "r"(b[nt][0]), "r"(b[nt][1]));
        }

        // ---- pos / exc extraction (2log2e*dot units) ----
        if (diag) {
            #pragma unroll
            for (int mt = 0; mt < 2; mt++)
                #pragma unroll
                for (int nt = 0; nt < 8; nt++)
                    #pragma unroll
                    for (int q = 0; q < 4; q++) {
                        int r_loc = wm + mt * 16 + (lane >> 2) + ((q & 2) << 2);
                        int c_loc = wn + nt * 8 + ((lane & 3) << 1) + (q & 1);
                        if (r_loc == c_loc)
                            g_pos[m0 + r_loc] = c[mt][nt][q];
                    }
        } else if (ni - mi == (HALF >> 7)) {
            #pragma unroll
            for (int mt = 0; mt < 2; mt++)
                #pragma unroll
                for (int nt = 0; nt < 8; nt++)
                    #pragma unroll
                    for (int q = 0; q < 4; q++) {
                        int r_loc = wm + mt * 16 + (lane >> 2) + ((q & 2) << 2);
                        int c_loc = wn + nt * 8 + ((lane & 3) << 1) + (q & 1);
                        if (r_loc == c_loc) {
                            float v = c[mt][nt][q];
                            g_exc[m0 + r_loc] = v;
                            g_exc[n0 + r_loc] = v;
                        }
                    }
        }

        // ---- epilogue: bare ex2; row sums + col sums ----
        float cs0[8], cs1[8];
        #pragma unroll
        for (int nt = 0; nt < 8; nt++) { cs0[nt] = 0.0f; cs1[nt] = 0.0f; }

        #pragma unroll
        for (int mt = 0; mt < 2; mt++) {
            float s0 = 0.0f, s1 = 0.0f;
            #pragma unroll
            for (int nt = 0; nt < 8; nt++) {
                float e0 = ex2_approx(c[mt][nt][0]);
                float e1 = ex2_approx(c[mt][nt][1]);
                float e2 = ex2_approx(c[mt][nt][2]);
                float e3 = ex2_approx(c[mt][nt][3]);
                s0 += e0 + e1;
                s1 += e2 + e3;
                cs0[nt] += e0 + e2;
                cs1[nt] += e1 + e3;
            }
            s0 += __shfl_xor_sync(0xFFFFFFFFu, s0, 1);
            s0 += __shfl_xor_sync(0xFFFFFFFFu, s0, 2);
            s1 += __shfl_xor_sync(0xFFFFFFFFu, s1, 1);
            s1 += __shfl_xor_sync(0xFFFFFFFFu, s1, 2);
            if ((lane & 3) == 0) {
                int r = m0 + wm + mt * 16 + (lane >> 2);
                atomicAdd(&g_rowsum[r],     s0);
                atomicAdd(&g_rowsum[r + 8], s1);
            }
        }

        if (!diag) {
            #pragma unroll
            for (int nt = 0; nt < 8; nt++) {
                float u = cs0[nt], v = cs1[nt];
                u += __shfl_xor_sync(0xFFFFFFFFu, u, 4);
                u += __shfl_xor_sync(0xFFFFFFFFu, u, 8);
                u += __shfl_xor_sync(0xFFFFFFFFu, u, 16);
                v += __shfl_xor_sync(0xFFFFFFFFu, v, 4);
                v += __shfl_xor_sync(0xFFFFFFFFu, v, 8);
                v += __shfl_xor_sync(0xFFFFFFFFu, v, 16);
                if (lane < 4) {
                    int cix = n0 + wn + nt * 8 + (lane << 1);
                    atomicAdd(&g_rowsum[cix],     u);
                    atomicAdd(&g_rowsum[cix + 1], v);
                }
            }
        }

        // ---- advance pipeline ----
        if (!last) {
            if (pf) {
                CP_WAIT0();
                __syncthreads();
                cur ^= 1;
            } else {
                __syncthreads();
                load_tile_async(sb + SMEM_A, mi_n << 7, tid);
                load_tile_async(sb + SMEM_B0 + (cur << 15), ni_n << 7, tid);
                CP_COMMIT();
                CP_WAIT0();
                __syncthreads();
            }
            mi = mi_n; ni = ni_n;
        }
    }

    // ======================= inline finalize (last CTA) =====================
    __syncthreads();
    __threadfence();
    __shared__ unsigned s_rank;
    if (tid == 0) s_rank = atomicAdd(&g_cnt, 1u);
    __syncthreads();
    if (s_rank == GRID_GRAM - 1) {
        float* red = reinterpret_cast<float*>(smem);
        float acc = 0.0f;
        for (int r = tid; r < N_TOTAL; r += 256) {
            float S = __ldcg(&g_rowsum[r]) - ex2_approx(__ldcg(&g_exc[r]));
            acc += logf(S) - __ldcg(&g_pos[r]) * INV_LOG2E;
        }
        red[tid] = acc;
        __syncthreads();
        #pragma unroll
        for (int st = 128; st > 0; st >>= 1) {
            if (tid < st) red[tid] += red[tid + st];
            __syncthreads();
        }
        if (tid == 0) out[0] = red[0] / (float)N_TOTAL;
    }
}

// ============================================================================
// launch
// ============================================================================
extern "C" void kernel_launch(void* const* d_in, const int* in_sizes, int n_in,
                              void* d_out, int out_size) {
    (void)in_sizes; (void)n_in; (void)out_size;
    const float* zi = (const float*)d_in[0];
    const float* zj = (const float*)d_in[1];
    float* out = (float*)d_out;

    normalize_kernel<<<N_TOTAL / 32, 256>>>(zi, zj);

    cudaFuncSetAttribute(gram_kernel,
                         cudaFuncAttributeMaxDynamicSharedMemorySize, SMEM_TOT);
    gram_kernel<<<GRID_GRAM, 256, SMEM_TOT>>>(out);
}

// round 10
// speedup vs baseline: 1.1712x; 1.1597x over previous
#include <cuda_runtime.h>
#include <cuda_bf16.h>
#include <cstdint>

// ============================================================================
// NT-Xent loss, GB300 (sm_103a) -- HMMA symmetric-Gram, persistent CTAs.
// R10 = R4 structure (the 39.4us winner) + sqrt(2log2e) prescale (bare-ex2
// epilogue) + 4-row MLP normalize. Separate 32-CTA finalize kernel.
// ============================================================================

#define N_TOTAL 8192
#define HALF    4096
#define DIM     128
#define INV_LOG2E  0.6931471805599453f
#define SQRT_T     1.6986435838080746f   // sqrt(2*log2(e))

#define GRID_GRAM 296

__device__ __nv_bfloat16 g_znb[N_TOTAL * DIM];   // rows scaled by SQRT_T
__device__ float g_rowsum[N_TOTAL];
__device__ float g_pos[N_TOTAL];                 // 2log2e * dot units
__device__ float g_exc[N_TOTAL];                 // 2log2e * dot units
__device__ float g_acc;
__device__ unsigned int g_cnt;

__device__ __forceinline__ uint32_t smem_to_u32(const void* p) {
    uint32_t a;
    asm("{ .reg .u64 t; cvta.to.shared.u64 t, %1; cvt.u32.u64 %0, t; }"
        : "=r"(a) : "l"(p));
    return a;
}
__device__ __forceinline__ float ex2_approx(float x) {
    float y;
    asm("ex2.approx.f32 %0, %1;" : "=f"(y) : "f"(x));
    return y;
}

// ============================================================================
// Kernel 1: normalize -> bf16 * SQRT_T. 4 rows per warp, loads front-batched.
// ============================================================================
__global__ void normalize_kernel(const float* __restrict__ zi,
                                 const float* __restrict__ zj) {
    int gw   = blockIdx.x * 8 + (threadIdx.x >> 5);   // 0..2047
    int lane = threadIdx.x & 31;
    int base = gw * 4;

    float4 v[4];
    #pragma unroll
    for (int k = 0; k < 4; k++) {
        int row = base + k;
        const float* src = (row < HALF) ? (zi + (size_t)row * DIM)
                                        : (zj + (size_t)(row - HALF) * DIM);
        v[k] = reinterpret_cast<const float4*>(src)[lane];
    }
    float ss[4];
    #pragma unroll
    for (int k = 0; k < 4; k++)
        ss[k] = v[k].x * v[k].x + v[k].y * v[k].y + v[k].z * v[k].z + v[k].w * v[k].w;
    #pragma unroll
    for (int o = 16; o; o >>= 1) {
        #pragma unroll
        for (int k = 0; k < 4; k++)
            ss[k] += __shfl_xor_sync(0xFFFFFFFFu, ss[k], o);
    }
    #pragma unroll
    for (int k = 0; k < 4; k++) {
        int row = base + k;
        float inv = SQRT_T / fmaxf(sqrtf(ss[k]), 1e-8f);
        __nv_bfloat162* dst =
            reinterpret_cast<__nv_bfloat162*>(g_znb + (size_t)row * DIM + lane * 4);
        dst[0] = __floats2bfloat162_rn(v[k].x * inv, v[k].y * inv);
        dst[1] = __floats2bfloat162_rn(v[k].z * inv, v[k].w * inv);
        if (lane == 0) g_rowsum[row] = 0.0f;
    }
    if (gw == 0 && lane == 0) { g_acc = 0.0f; g_cnt = 0u; }
}

// ============================================================================
// Kernel 2: persistent symmetric Gram GEMM (R4 structure, bare-ex2 epilogue)
// smem: A 32KB | B0 32KB | B1 32KB
// ============================================================================
#define SMEM_A   0
#define SMEM_B0  32768
#define SMEM_TOT 98304

__device__ __forceinline__ uint32_t tile_off(int row, int chunk16) {
    return (uint32_t)(row * 256 + ((chunk16 ^ (row & 7)) << 4));
}

__device__ __forceinline__ void load_tile_async(uint32_t sdst, int row0, int tid) {
    const uint4* gp = reinterpret_cast<const uint4*>(g_znb + (size_t)row0 * DIM);
    #pragma unroll
    for (int it = 0; it < 8; it++) {
        int idx = tid + it * 256;
        int row = idx >> 4, ch = idx & 15;
        asm volatile("cp.async.cg.shared.global [%0], [%1], 16;"
            :: "r"(sdst + tile_off(row, ch)), "l"(gp + (row << 4) + ch));
    }
}
#define CP_COMMIT() asm volatile("cp.async.commit_group;" ::: "memory")
#define CP_WAIT0()  asm volatile("cp.async.wait_group 0;"  ::: "memory")

__global__ void __launch_bounds__(256, 2)
gram_kernel() {
    extern __shared__ char smem[];
    uint32_t sb = smem_to_u32(smem);
    const int tid  = threadIdx.x;
    const int wid  = tid >> 5;
    const int lane = tid & 31;
    const int bid  = blockIdx.x;

    const int start = bid * 7 + (bid < 8 ? bid : 8);
    const int count = (bid < 8) ? 8 : 7;

    int mi = 0, rem = start, len = 64;
    while (rem >= len) { rem -= len; len--; mi++; }
    int ni = mi + rem;

    const int wm = (wid & 3) * 32;
    const int wn = (wid >> 2) * 64;
    const int l7 = lane & 7;
    const int g  = lane >> 3;

    load_tile_async(sb + SMEM_A, mi << 7, tid);
    load_tile_async(sb + SMEM_B0, ni << 7, tid);
    CP_COMMIT();
    CP_WAIT0();
    __syncthreads();
    int cur = 0;

    for (int i = 0; i < count; i++) {
        const int m0 = mi << 7, n0 = ni << 7;
        const bool diag = (mi == ni);
        const bool last = (i == count - 1);
        int mi_n = mi, ni_n = ni + 1;
        if (ni_n == 64) { mi_n = mi + 1; ni_n = mi_n; }
        const bool pf = !last && (mi_n == mi);
        if (pf) {
            load_tile_async(sb + SMEM_B0 + ((1 - cur) << 15), ni_n << 7, tid);
            CP_COMMIT();
        }
        const uint32_t bbase = sb + SMEM_B0 + (cur << 15);

        // ---- MMA mainloop ----
        float c[2][8][4];
        #pragma unroll
        for (int mt = 0; mt < 2; mt++)
            #pragma unroll
            for (int nt = 0; nt < 8; nt++)
                #pragma unroll
                for (int q = 0; q < 4; q++) c[mt][nt][q] = 0.0f;

        #pragma unroll
        for (int ks = 0; ks < 8; ks++) {
            uint32_t a[2][4];
            #pragma unroll
            for (int mt = 0; mt < 2; mt++) {
                int row = wm + mt * 16 + l7 + ((g & 1) << 3);
                uint32_t addr = sb + SMEM_A + tile_off(row, ks * 2 + (g >> 1));
                asm volatile(
                    "ldmatrix.sync.aligned.m8n8.x4.shared.b16 {%0,%1,%2,%3}, [%4];"
                    : "=r"(a[mt][0]), "=r"(a[mt][1]), "=r"(a[mt][2]), "=r"(a[mt][3])
                    : "r"(addr));
            }
            uint32_t b[8][2];
            #pragma unroll
            for (int nt2 = 0; nt2 < 4; nt2++) {
                int row = wn + nt2 * 16 + l7 + ((g >> 1) << 3);
                uint32_t addr = bbase + tile_off(row, ks * 2 + (g & 1));
                asm volatile(
                    "ldmatrix.sync.aligned.m8n8.x4.shared.b16 {%0,%1,%2,%3}, [%4];"
                    : "=r"(b[nt2 * 2][0]),     "=r"(b[nt2 * 2][1]),
                      "=r"(b[nt2 * 2 + 1][0]), "=r"(b[nt2 * 2 + 1][1])
                    : "r"(addr));
            }
            #pragma unroll
            for (int mt = 0; mt < 2; mt++)
                #pragma unroll
                for (int nt = 0; nt < 8; nt++)
                    asm volatile(
                        "mma.sync.aligned.m16n8k16.row.col.f32.bf16.bf16.f32 "
                        "{%0,%1,%2,%3}, {%4,%5,%6,%7}, {%8,%9}, {%0,%1,%2,%3};"
                        : "+f"(c[mt][nt][0]), "+f"(c[mt][nt][1]),
                          "+f"(c[mt][nt][2]), "+f"(c[mt][nt][3])
                        : "r"(a[mt][0]), "r"(a[mt][1]), "r"(a[mt][2]), "r"(a[mt][3]),
                          "r"(b[nt][0]), "r"(b[nt][1]));
        }

        // ---- pos / exc extraction (2log2e*dot units) ----
        if (diag) {
            #pragma unroll
            for (int mt = 0; mt < 2; mt++)
                #pragma unroll
                for (int nt = 0; nt < 8; nt++)
                    #pragma unroll
                    for (int q = 0; q < 4; q++) {
                        int r_loc = wm + mt * 16 + (lane >> 2) + ((q & 2) << 2);
                        int c_loc = wn + nt * 8 + ((lane & 3) << 1) + (q & 1);
                        if (r_loc == c_loc)
                            g_pos[m0 + r_loc] = c[mt][nt][q];
                    }
        } else if (ni - mi == (HALF >> 7)) {
            #pragma unroll
            for (int mt = 0; mt < 2; mt++)
                #pragma unroll
                for (int nt = 0; nt < 8; nt++)
                    #pragma unroll
                    for (int q = 0; q < 4; q++) {
                        int r_loc = wm + mt * 16 + (lane >> 2) + ((q & 2) << 2);
                        int c_loc = wn + nt * 8 + ((lane & 3) << 1) + (q & 1);
                        if (r_loc == c_loc) {
                            float v = c[mt][nt][q];
                            g_exc[m0 + r_loc] = v;
                            g_exc[n0 + r_loc] = v;
                        }
                    }
        }

        // ---- epilogue: bare ex2; row sums + col sums ----
        float cs0[8], cs1[8];
        #pragma unroll
        for (int nt = 0; nt < 8; nt++) { cs0[nt] = 0.0f; cs1[nt] = 0.0f; }

        #pragma unroll
        for (int mt = 0; mt < 2; mt++) {
            float s0 = 0.0f, s1 = 0.0f;
            #pragma unroll
            for (int nt = 0; nt < 8; nt++) {
                float e0 = ex2_approx(c[mt][nt][0]);
                float e1 = ex2_approx(c[mt][nt][1]);
                float e2 = ex2_approx(c[mt][nt][2]);
                float e3 = ex2_approx(c[mt][nt][3]);
                s0 += e0 + e1;
                s1 += e2 + e3;
                cs0[nt] += e0 + e2;
                cs1[nt] += e1 + e3;
            }
            s0 += __shfl_xor_sync(0xFFFFFFFFu, s0, 1);
            s0 += __shfl_xor_sync(0xFFFFFFFFu, s0, 2);
            s1 += __shfl_xor_sync(0xFFFFFFFFu, s1, 1);
            s1 += __shfl_xor_sync(0xFFFFFFFFu, s1, 2);
            if ((lane & 3) == 0) {
                int r = m0 + wm + mt * 16 + (lane >> 2);
                atomicAdd(&g_rowsum[r],     s0);
                atomicAdd(&g_rowsum[r + 8], s1);
            }
        }

        if (!diag) {
            #pragma unroll
            for (int nt = 0; nt < 8; nt++) {
                float u = cs0[nt], v = cs1[nt];
                u += __shfl_xor_sync(0xFFFFFFFFu, u, 4);
                u += __shfl_xor_sync(0xFFFFFFFFu, u, 8);
                u += __shfl_xor_sync(0xFFFFFFFFu, u, 16);
                v += __shfl_xor_sync(0xFFFFFFFFu, v, 4);
                v += __shfl_xor_sync(0xFFFFFFFFu, v, 8);
                v += __shfl_xor_sync(0xFFFFFFFFu, v, 16);
                if (lane < 4) {
                    int cix = n0 + wn + nt * 8 + (lane << 1);
                    atomicAdd(&g_rowsum[cix],     u);
                    atomicAdd(&g_rowsum[cix + 1], v);
                }
            }
        }

        // ---- advance pipeline ----
        if (!last) {
            if (pf) {
                CP_WAIT0();
                __syncthreads();
                cur ^= 1;
            } else {
                __syncthreads();
                load_tile_async(sb + SMEM_A, mi_n << 7, tid);
                load_tile_async(sb + SMEM_B0 + (cur << 15), ni_n << 7, tid);
                CP_COMMIT();
                CP_WAIT0();
                __syncthreads();
            }
            mi = mi_n; ni = ni_n;
        }
    }
}

// ============================================================================
// Kernel 3: finalize -> scalar loss (32 CTAs, last block writes)
// ============================================================================
__global__ void finalize_kernel(float* __restrict__ out) {
    __shared__ float red[256];
    int r = blockIdx.x * 256 + threadIdx.x;
    float S = g_rowsum[r] - ex2_approx(g_exc[r]);
    float acc = logf(S) - g_pos[r] * INV_LOG2E;
    red[threadIdx.x] = acc;
    __syncthreads();
    #pragma unroll
    for (int s = 128; s > 0; s >>= 1) {
        if (threadIdx.x < s) red[threadIdx.x] += red[threadIdx.x + s];
        __syncthreads();
    }
    if (threadIdx.x == 0) {
        atomicAdd(&g_acc, red[0]);
        __threadfence();
        unsigned done = atomicAdd(&g_cnt, 1u);
        if (done == gridDim.x - 1) {
            float total = atomicAdd(&g_acc, 0.0f);
            out[0] = total / (float)N_TOTAL;
        }
    }
}

// ============================================================================
// launch
// ============================================================================
extern "C" void kernel_launch(void* const* d_in, const int* in_sizes, int n_in,
                              void* d_out, int out_size) {
    (void)in_sizes; (void)n_in; (void)out_size;
    const float* zi = (const float*)d_in[0];
    const float* zj = (const float*)d_in[1];
    float* out = (float*)d_out;

    normalize_kernel<<<N_TOTAL / 32, 256>>>(zi, zj);

    cudaFuncSetAttribute(gram_kernel,
                         cudaFuncAttributeMaxDynamicSharedMemorySize, SMEM_TOT);
    gram_kernel<<<GRID_GRAM, 256, SMEM_TOT>>>();

    finalize_kernel<<<N_TOTAL / 256, 256>>>(out);
}

// round 11
// speedup vs baseline: 1.2797x; 1.0926x over previous
#include <cuda_runtime.h>
#include <cuda_bf16.h>
#include <cuda_fp16.h>
#include <cstdint>

// ============================================================================
// NT-Xent loss, GB300 (sm_103a) -- HMMA symmetric-Gram, persistent CTAs.
// R11 = R10 + packed f16x2 epilogue: ex2.approx.f16x2 (2 exps/MUFU op),
// half2 HADD2 partial sums, half2 shuffle reduction.
// ============================================================================

#define N_TOTAL 8192
#define HALF    4096
#define DIM     128
#define INV_LOG2E  0.6931471805599453f
#define SQRT_T     1.6986435838080746f   // sqrt(2*log2(e))

#define GRID_GRAM 296

__device__ __nv_bfloat16 g_znb[N_TOTAL * DIM];   // rows scaled by SQRT_T
__device__ float g_rowsum[N_TOTAL];
__device__ float g_pos[N_TOTAL];                 // 2log2e * dot units
__device__ float g_exc[N_TOTAL];                 // 2log2e * dot units
__device__ float g_acc;
__device__ unsigned int g_cnt;

__device__ __forceinline__ uint32_t smem_to_u32(const void* p) {
    uint32_t a;
    asm("{ .reg .u64 t; cvta.to.shared.u64 t, %1; cvt.u32.u64 %0, t; }"
        : "=r"(a) : "l"(p));
    return a;
}
__device__ __forceinline__ float ex2_approx(float x) {
    float y;
    asm("ex2.approx.f32 %0, %1;" : "=f"(y) : "f"(x));
    return y;
}
// pack (lo, hi) floats -> half2 bits
__device__ __forceinline__ uint32_t pack_h2(float lo, float hi) {
    uint32_t r;
    asm("cvt.rn.f16x2.f32 %0, %1, %2;" : "=r"(r) : "f"(hi), "f"(lo));
    return r;
}
__device__ __forceinline__ uint32_t ex2_h2(uint32_t x) {
    uint32_t r;
    asm("ex2.approx.f16x2 %0, %1;" : "=r"(r) : "r"(x));
    return r;
}
__device__ __forceinline__ uint32_t hadd2b(uint32_t a, uint32_t b) {
    uint32_t r;
    asm("add.f16x2 %0, %1, %2;" : "=r"(r) : "r"(a), "r"(b));
    return r;
}
__device__ __forceinline__ float2 unpack_h2(uint32_t v) {
    __half2 h = *reinterpret_cast<__half2*>(&v);
    return __half22float2(h);
}

// ============================================================================
// Kernel 1: normalize -> bf16 * SQRT_T. 4 rows per warp, loads front-batched.
// ============================================================================
__global__ void normalize_kernel(const float* __restrict__ zi,
                                 const float* __restrict__ zj) {
    int gw   = blockIdx.x * 8 + (threadIdx.x >> 5);
    int lane = threadIdx.x & 31;
    int base = gw * 4;

    float4 v[4];
    #pragma unroll
    for (int k = 0; k < 4; k++) {
        int row = base + k;
        const float* src = (row < HALF) ? (zi + (size_t)row * DIM)
                                        : (zj + (size_t)(row - HALF) * DIM);
        v[k] = reinterpret_cast<const float4*>(src)[lane];
    }
    float ss[4];
    #pragma unroll
    for (int k = 0; k < 4; k++)
        ss[k] = v[k].x * v[k].x + v[k].y * v[k].y + v[k].z * v[k].z + v[k].w * v[k].w;
    #pragma unroll
    for (int o = 16; o; o >>= 1) {
        #pragma unroll
        for (int k = 0; k < 4; k++)
            ss[k] += __shfl_xor_sync(0xFFFFFFFFu, ss[k], o);
    }
    #pragma unroll
    for (int k = 0; k < 4; k++) {
        int row = base + k;
        float inv = SQRT_T / fmaxf(sqrtf(ss[k]), 1e-8f);
        __nv_bfloat162* dst =
            reinterpret_cast<__nv_bfloat162*>(g_znb + (size_t)row * DIM + lane * 4);
        dst[0] = __floats2bfloat162_rn(v[k].x * inv, v[k].y * inv);
        dst[1] = __floats2bfloat162_rn(v[k].z * inv, v[k].w * inv);
        if (lane == 0) g_rowsum[row] = 0.0f;
    }
    if (gw == 0 && lane == 0) { g_acc = 0.0f; g_cnt = 0u; }
}

// ============================================================================
// Kernel 2: persistent symmetric Gram GEMM (R4 structure, f16x2 epilogue)
// smem: A 32KB | B0 32KB | B1 32KB
// ============================================================================
#define SMEM_A   0
#define SMEM_B0  32768
#define SMEM_TOT 98304

__device__ __forceinline__ uint32_t tile_off(int row, int chunk16) {
    return (uint32_t)(row * 256 + ((chunk16 ^ (row & 7)) << 4));
}

__device__ __forceinline__ void load_tile_async(uint32_t sdst, int row0, int tid) {
    const uint4* gp = reinterpret_cast<const uint4*>(g_znb + (size_t)row0 * DIM);
    #pragma unroll
    for (int it = 0; it < 8; it++) {
        int idx = tid + it * 256;
        int row = idx >> 4, ch = idx & 15;
        asm volatile("cp.async.cg.shared.global [%0], [%1], 16;"
            :: "r"(sdst + tile_off(row, ch)), "l"(gp + (row << 4) + ch));
    }
}
#define CP_COMMIT() asm volatile("cp.async.commit_group;" ::: "memory")
#define CP_WAIT0()  asm volatile("cp.async.wait_group 0;"  ::: "memory")

__global__ void __launch_bounds__(256, 2)
gram_kernel() {
    extern __shared__ char smem[];
    uint32_t sb = smem_to_u32(smem);
    const int tid  = threadIdx.x;
    const int wid  = tid >> 5;
    const int lane = tid & 31;
    const int bid  = blockIdx.x;

    const int start = bid * 7 + (bid < 8 ? bid : 8);
    const int count = (bid < 8) ? 8 : 7;

    int mi = 0, rem = start, len = 64;
    while (rem >= len) { rem -= len; len--; mi++; }
    int ni = mi + rem;

    const int wm = (wid & 3) * 32;
    const int wn = (wid >> 2) * 64;
    const int l7 = lane & 7;
    const int g  = lane >> 3;

    load_tile_async(sb + SMEM_A, mi << 7, tid);
    load_tile_async(sb + SMEM_B0, ni << 7, tid);
    CP_COMMIT();
    CP_WAIT0();
    __syncthreads();
    int cur = 0;

    for (int i = 0; i < count; i++) {
        const int m0 = mi << 7, n0 = ni << 7;
        const bool diag = (mi == ni);
        const bool last = (i == count - 1);
        int mi_n = mi, ni_n = ni + 1;
        if (ni_n == 64) { mi_n = mi + 1; ni_n = mi_n; }
        const bool pf = !last && (mi_n == mi);
        if (pf) {
            load_tile_async(sb + SMEM_B0 + ((1 - cur) << 15), ni_n << 7, tid);
            CP_COMMIT();
        }
        const uint32_t bbase = sb + SMEM_B0 + (cur << 15);

        // ---- MMA mainloop ----
        float c[2][8][4];
        #pragma unroll
        for (int mt = 0; mt < 2; mt++)
            #pragma unroll
            for (int nt = 0; nt < 8; nt++)
                #pragma unroll
                for (int q = 0; q < 4; q++) c[mt][nt][q] = 0.0f;

        #pragma unroll
        for (int ks = 0; ks < 8; ks++) {
            uint32_t a[2][4];
            #pragma unroll
            for (int mt = 0; mt < 2; mt++) {
                int row = wm + mt * 16 + l7 + ((g & 1) << 3);
                uint32_t addr = sb + SMEM_A + tile_off(row, ks * 2 + (g >> 1));
                asm volatile(
                    "ldmatrix.sync.aligned.m8n8.x4.shared.b16 {%0,%1,%2,%3}, [%4];"
                    : "=r"(a[mt][0]), "=r"(a[mt][1]), "=r"(a[mt][2]), "=r"(a[mt][3])
                    : "r"(addr));
            }
            uint32_t b[8][2];
            #pragma unroll
            for (int nt2 = 0; nt2 < 4; nt2++) {
                int row = wn + nt2 * 16 + l7 + ((g >> 1) << 3);
                uint32_t addr = bbase + tile_off(row, ks * 2 + (g & 1));
                asm volatile(
                    "ldmatrix.sync.aligned.m8n8.x4.shared.b16 {%0,%1,%2,%3}, [%4];"
                    : "=r"(b[nt2 * 2][0]),     "=r"(b[nt2 * 2][1]),
                      "=r"(b[nt2 * 2 + 1][0]), "=r"(b[nt2 * 2 + 1][1])
                    : "r"(addr));
            }
            #pragma unroll
            for (int mt = 0; mt < 2; mt++)
                #pragma unroll
                for (int nt = 0; nt < 8; nt++)
                    asm volatile(
                        "mma.sync.aligned.m16n8k16.row.col.f32.bf16.bf16.f32 "
                        "{%0,%1,%2,%3}, {%4,%5,%6,%7}, {%8,%9}, {%0,%1,%2,%3};"
                        : "+f"(c[mt][nt][0]), "+f"(c[mt][nt][1]),
                          "+f"(c[mt][nt][2]), "+f"(c[mt][nt][3])
                        : "r"(a[mt][0]), "r"(a[mt][1]), "r"(a[mt][2]), "r"(a[mt][3]),
                          "r"(b[nt][0]), "r"(b[nt][1]));
        }

        // ---- pos / exc extraction (2log2e*dot units) ----
        if (diag) {
            #pragma unroll
            for (int mt = 0; mt < 2; mt++)
                #pragma unroll
                for (int nt = 0; nt < 8; nt++)
                    #pragma unroll
                    for (int q = 0; q < 4; q++) {
                        int r_loc = wm + mt * 16 + (lane >> 2) + ((q & 2) << 2);
                        int c_loc = wn + nt * 8 + ((lane & 3) << 1) + (q & 1);
                        if (r_loc == c_loc)
                            g_pos[m0 + r_loc] = c[mt][nt][q];
                    }
        } else if (ni - mi == (HALF >> 7)) {
            #pragma unroll
            for (int mt = 0; mt < 2; mt++)
                #pragma unroll
                for (int nt = 0; nt < 8; nt++)
                    #pragma unroll
                    for (int q = 0; q < 4; q++) {
                        int r_loc = wm + mt * 16 + (lane >> 2) + ((q & 2) << 2);
                        int c_loc = wn + nt * 8 + ((lane & 3) << 1) + (q & 1);
                        if (r_loc == c_loc) {
                            float v = c[mt][nt][q];
                            g_exc[m0 + r_loc] = v;
                            g_exc[n0 + r_loc] = v;
                        }
                    }
        }

        // ---- f16x2 epilogue ----
        // quad layout: q0=(r,c) q1=(r,c+1) q2=(r+8,c) q3=(r+8,c+1)
        // p01 = exps of (c,c+1) for row r; p23 = same cols, row r+8
        uint32_t rs01[2], rs23[2], csv[8];
        #pragma unroll
        for (int mt = 0; mt < 2; mt++) { rs01[mt] = 0u; rs23[mt] = 0u; }
        #pragma unroll
        for (int nt = 0; nt < 8; nt++) csv[nt] = 0u;

        #pragma unroll
        for (int mt = 0; mt < 2; mt++) {
            #pragma unroll
            for (int nt = 0; nt < 8; nt++) {
                uint32_t p01 = ex2_h2(pack_h2(c[mt][nt][0], c[mt][nt][1]));
                uint32_t p23 = ex2_h2(pack_h2(c[mt][nt][2], c[mt][nt][3]));
                rs01[mt] = hadd2b(rs01[mt], p01);
                rs23[mt] = hadd2b(rs23[mt], p23);
                csv[nt]  = hadd2b(csv[nt], hadd2b(p01, p23));
            }
        }

        // row sums: reduce over (lane&3) group; lanes differ only in columns
        #pragma unroll
        for (int mt = 0; mt < 2; mt++) {
            uint32_t u = rs01[mt], w = rs23[mt];
            u = hadd2b(u, __shfl_xor_sync(0xFFFFFFFFu, u, 1));
            u = hadd2b(u, __shfl_xor_sync(0xFFFFFFFFu, u, 2));
            w = hadd2b(w, __shfl_xor_sync(0xFFFFFFFFu, w, 1));
            w = hadd2b(w, __shfl_xor_sync(0xFFFFFFFFu, w, 2));
            if ((lane & 3) == 0) {
                int r = m0 + wm + mt * 16 + (lane >> 2);
                float2 f0 = unpack_h2(u);
                float2 f1 = unpack_h2(w);
                atomicAdd(&g_rowsum[r],     f0.x + f0.y);
                atomicAdd(&g_rowsum[r + 8], f1.x + f1.y);
            }
        }

        // col sums: reduce over (lane>>2) replicas (rows); only off-diag tiles
        if (!diag) {
            #pragma unroll
            for (int nt = 0; nt < 8; nt++) {
                uint32_t u = csv[nt];
                u = hadd2b(u, __shfl_xor_sync(0xFFFFFFFFu, u, 4));
                u = hadd2b(u, __shfl_xor_sync(0xFFFFFFFFu, u, 8));
                u = hadd2b(u, __shfl_xor_sync(0xFFFFFFFFu, u, 16));
                if (lane < 4) {
                    float2 f = unpack_h2(u);
                    int cix = n0 + wn + nt * 8 + (lane << 1);
                    atomicAdd(&g_rowsum[cix],     f.x);
                    atomicAdd(&g_rowsum[cix + 1], f.y);
                }
            }
        }

        // ---- advance pipeline ----
        if (!last) {
            if (pf) {
                CP_WAIT0();
                __syncthreads();
                cur ^= 1;
            } else {
                __syncthreads();
                load_tile_async(sb + SMEM_A, mi_n << 7, tid);
                load_tile_async(sb + SMEM_B0 + (cur << 15), ni_n << 7, tid);
                CP_COMMIT();
                CP_WAIT0();
                __syncthreads();
            }
            mi = mi_n; ni = ni_n;
        }
    }
}

// ============================================================================
// Kernel 3: finalize -> scalar loss (32 CTAs, last block writes)
// ============================================================================
__global__ void finalize_kernel(float* __restrict__ out) {
    __shared__ float red[256];
    int r = blockIdx.x * 256 + threadIdx.x;
    float S = g_rowsum[r] - ex2_approx(g_exc[r]);
    float acc = logf(S) - g_pos[r] * INV_LOG2E;
    red[threadIdx.x] = acc;
    __syncthreads();
    #pragma unroll
    for (int s = 128; s > 0; s >>= 1) {
        if (threadIdx.x < s) red[threadIdx.x] += red[threadIdx.x + s];
        __syncthreads();
    }
    if (threadIdx.x == 0) {
        atomicAdd(&g_acc, red[0]);
        __threadfence();
        unsigned done = atomicAdd(&g_cnt, 1u);
        if (done == gridDim.x - 1) {
            float total = atomicAdd(&g_acc, 0.0f);
            out[0] = total / (float)N_TOTAL;
        }
    }
}

// ============================================================================
// launch
// ============================================================================
extern "C" void kernel_launch(void* const* d_in, const int* in_sizes, int n_in,
                              void* d_out, int out_size) {
    (void)in_sizes; (void)n_in; (void)out_size;
    const float* zi = (const float*)d_in[0];
    const float* zj = (const float*)d_in[1];
    float* out = (float*)d_out;

    normalize_kernel<<<N_TOTAL / 32, 256>>>(zi, zj);

    cudaFuncSetAttribute(gram_kernel,
                         cudaFuncAttributeMaxDynamicSharedMemorySize, SMEM_TOT);
    gram_kernel<<<GRID_GRAM, 256, SMEM_TOT>>>();

    finalize_kernel<<<N_TOTAL / 256, 256>>>(out);
}

// round 12
// speedup vs baseline: 1.2889x; 1.0072x over previous
#include <cuda_runtime.h>
#include <cuda_fp16.h>
#include <cstdint>

// ============================================================================
// NT-Xent loss, GB300 (sm_103a) -- HMMA symmetric-Gram, persistent CTAs.
// R12 = R11 + fp16-accumulator MMA (f16.f16.f16.f16): D frags are pre-packed
// half2 -> ex2.approx.f16x2 directly on accumulators (no cvt), 32 fewer regs.
// pos == 2.0 exactly (self-dot/T), so diag extraction is gone.
// ============================================================================

#define N_TOTAL 8192
#define HALF    4096
#define DIM     128
#define SQRT_T     1.6986435838080746f   // sqrt(2*log2(e))

#define GRID_GRAM 296

__device__ __half g_znh[N_TOTAL * DIM];          // rows scaled by SQRT_T
__device__ float g_rowsum[N_TOTAL];
__device__ float g_exc[N_TOTAL];                 // 2log2e * dot units
__device__ float g_acc;
__device__ unsigned int g_cnt;

__device__ __forceinline__ uint32_t smem_to_u32(const void* p) {
    uint32_t a;
    asm("{ .reg .u64 t; cvta.to.shared.u64 t, %1; cvt.u32.u64 %0, t; }"
        : "=r"(a) : "l"(p));
    return a;
}
__device__ __forceinline__ float ex2_approx(float x) {
    float y;
    asm("ex2.approx.f32 %0, %1;" : "=f"(y) : "f"(x));
    return y;
}
__device__ __forceinline__ uint32_t ex2_h2(uint32_t x) {
    uint32_t r;
    asm("ex2.approx.f16x2 %0, %1;" : "=r"(r) : "r"(x));
    return r;
}
__device__ __forceinline__ uint32_t hadd2b(uint32_t a, uint32_t b) {
    uint32_t r;
    asm("add.f16x2 %0, %1, %2;" : "=r"(r) : "r"(a), "r"(b));
    return r;
}
__device__ __forceinline__ float2 unpack_h2(uint32_t v) {
    __half2 h = *reinterpret_cast<__half2*>(&v);
    return __half22float2(h);
}

// ============================================================================
// Kernel 1: normalize -> fp16 * SQRT_T. 4 rows per warp, loads front-batched.
// ============================================================================
__global__ void normalize_kernel(const float* __restrict__ zi,
                                 const float* __restrict__ zj) {
    int gw   = blockIdx.x * 8 + (threadIdx.x >> 5);
    int lane = threadIdx.x & 31;
    int base = gw * 4;

    float4 v[4];
    #pragma unroll
    for (int k = 0; k < 4; k++) {
        int row = base + k;
        const float* src = (row < HALF) ? (zi + (size_t)row * DIM)
                                        : (zj + (size_t)(row - HALF) * DIM);
        v[k] = reinterpret_cast<const float4*>(src)[lane];
    }
    float ss[4];
    #pragma unroll
    for (int k = 0; k < 4; k++)
        ss[k] = v[k].x * v[k].x + v[k].y * v[k].y + v[k].z * v[k].z + v[k].w * v[k].w;
    #pragma unroll
    for (int o = 16; o; o >>= 1) {
        #pragma unroll
        for (int k = 0; k < 4; k++)
            ss[k] += __shfl_xor_sync(0xFFFFFFFFu, ss[k], o);
    }
    #pragma unroll
    for (int k = 0; k < 4; k++) {
        int row = base + k;
        float inv = SQRT_T / fmaxf(sqrtf(ss[k]), 1e-8f);
        __half2* dst =
            reinterpret_cast<__half2*>(g_znh + (size_t)row * DIM + lane * 4);
        dst[0] = __floats2half2_rn(v[k].x * inv, v[k].y * inv);
        dst[1] = __floats2half2_rn(v[k].z * inv, v[k].w * inv);
        if (lane == 0) g_rowsum[row] = 0.0f;
    }
    if (gw == 0 && lane == 0) { g_acc = 0.0f; g_cnt = 0u; }
}

// ============================================================================
// Kernel 2: persistent symmetric Gram GEMM (f16-accum HMMA, f16x2 epilogue)
// smem: A 32KB | B0 32KB | B1 32KB
// ============================================================================
#define SMEM_A   0
#define SMEM_B0  32768
#define SMEM_TOT 98304

__device__ __forceinline__ uint32_t tile_off(int row, int chunk16) {
    return (uint32_t)(row * 256 + ((chunk16 ^ (row & 7)) << 4));
}

__device__ __forceinline__ void load_tile_async(uint32_t sdst, int row0, int tid) {
    const uint4* gp = reinterpret_cast<const uint4*>(g_znh + (size_t)row0 * DIM);
    #pragma unroll
    for (int it = 0; it < 8; it++) {
        int idx = tid + it * 256;
        int row = idx >> 4, ch = idx & 15;
        asm volatile("cp.async.cg.shared.global [%0], [%1], 16;"
            :: "r"(sdst + tile_off(row, ch)), "l"(gp + (row << 4) + ch));
    }
}
#define CP_COMMIT() asm volatile("cp.async.commit_group;" ::: "memory")
#define CP_WAIT0()  asm volatile("cp.async.wait_group 0;"  ::: "memory")

__global__ void __launch_bounds__(256, 2)
gram_kernel() {
    extern __shared__ char smem[];
    uint32_t sb = smem_to_u32(smem);
    const int tid  = threadIdx.x;
    const int wid  = tid >> 5;
    const int lane = tid & 31;
    const int bid  = blockIdx.x;

    const int start = bid * 7 + (bid < 8 ? bid : 8);
    const int count = (bid < 8) ? 8 : 7;

    int mi = 0, rem = start, len = 64;
    while (rem >= len) { rem -= len; len--; mi++; }
    int ni = mi + rem;

    const int wm = (wid & 3) * 32;
    const int wn = (wid >> 2) * 64;
    const int l7 = lane & 7;
    const int g  = lane >> 3;

    load_tile_async(sb + SMEM_A, mi << 7, tid);
    load_tile_async(sb + SMEM_B0, ni << 7, tid);
    CP_COMMIT();
    CP_WAIT0();
    __syncthreads();
    int cur = 0;

    for (int i = 0; i < count; i++) {
        const int m0 = mi << 7, n0 = ni << 7;
        const bool diag = (mi == ni);
        const bool last = (i == count - 1);
        int mi_n = mi, ni_n = ni + 1;
        if (ni_n == 64) { mi_n = mi + 1; ni_n = mi_n; }
        const bool pf = !last && (mi_n == mi);
        if (pf) {
            load_tile_async(sb + SMEM_B0 + ((1 - cur) << 15), ni_n << 7, tid);
            CP_COMMIT();
        }
        const uint32_t bbase = sb + SMEM_B0 + (cur << 15);

        // ---- MMA mainloop (fp16 accumulate) ----
        // acc[mt][nt][0] = half2(row r:   col c, c+1)
        // acc[mt][nt][1] = half2(row r+8: col c, c+1)
        uint32_t acc[2][8][2];
        #pragma unroll
        for (int mt = 0; mt < 2; mt++)
            #pragma unroll
            for (int nt = 0; nt < 8; nt++) { acc[mt][nt][0] = 0u; acc[mt][nt][1] = 0u; }

        #pragma unroll
        for (int ks = 0; ks < 8; ks++) {
            uint32_t a[2][4];
            #pragma unroll
            for (int mt = 0; mt < 2; mt++) {
                int row = wm + mt * 16 + l7 + ((g & 1) << 3);
                uint32_t addr = sb + SMEM_A + tile_off(row, ks * 2 + (g >> 1));
                asm volatile(
                    "ldmatrix.sync.aligned.m8n8.x4.shared.b16 {%0,%1,%2,%3}, [%4];"
                    : "=r"(a[mt][0]), "=r"(a[mt][1]), "=r"(a[mt][2]), "=r"(a[mt][3])
                    : "r"(addr));
            }
            uint32_t b[8][2];
            #pragma unroll
            for (int nt2 = 0; nt2 < 4; nt2++) {
                int row = wn + nt2 * 16 + l7 + ((g >> 1) << 3);
                uint32_t addr = bbase + tile_off(row, ks * 2 + (g & 1));
                asm volatile(
                    "ldmatrix.sync.aligned.m8n8.x4.shared.b16 {%0,%1,%2,%3}, [%4];"
                    : "=r"(b[nt2 * 2][0]),     "=r"(b[nt2 * 2][1]),
                      "=r"(b[nt2 * 2 + 1][0]), "=r"(b[nt2 * 2 + 1][1])
                    : "r"(addr));
            }
            #pragma unroll
            for (int mt = 0; mt < 2; mt++)
                #pragma unroll
                for (int nt = 0; nt < 8; nt++)
                    asm volatile(
                        "mma.sync.aligned.m16n8k16.row.col.f16.f16.f16.f16 "
                        "{%0,%1}, {%2,%3,%4,%5}, {%6,%7}, {%0,%1};"
                        : "+r"(acc[mt][nt][0]), "+r"(acc[mt][nt][1])
                        : "r"(a[mt][0]), "r"(a[mt][1]), "r"(a[mt][2]), "r"(a[mt][3]),
                          "r"(b[nt][0]), "r"(b[nt][1]));
        }

        // ---- exc extraction (2log2e*dot units); pos is the constant 2.0 ----
        if (ni - mi == (HALF >> 7)) {
            #pragma unroll
            for (int mt = 0; mt < 2; mt++)
                #pragma unroll
                for (int nt = 0; nt < 8; nt++)
                    #pragma unroll
                    for (int q = 0; q < 4; q++) {
                        int r_loc = wm + mt * 16 + (lane >> 2) + ((q & 2) << 2);
                        int c_loc = wn + nt * 8 + ((lane & 3) << 1) + (q & 1);
                        if (r_loc == c_loc) {
                            __half2 h = *reinterpret_cast<__half2*>(&acc[mt][nt][q >> 1]);
                            float v = __half2float((q & 1) ? __high2half(h)
                                                           : __low2half(h));
                            g_exc[m0 + r_loc] = v;
                            g_exc[n0 + r_loc] = v;
                        }
                    }
        }

        // ---- f16x2 epilogue: ex2 straight on accumulator regs ----
        uint32_t rs01[2], rs23[2], csv[8];
        #pragma unroll
        for (int mt = 0; mt < 2; mt++) { rs01[mt] = 0u; rs23[mt] = 0u; }
        #pragma unroll
        for (int nt = 0; nt < 8; nt++) csv[nt] = 0u;

        #pragma unroll
        for (int mt = 0; mt < 2; mt++) {
            #pragma unroll
            for (int nt = 0; nt < 8; nt++) {
                uint32_t p01 = ex2_h2(acc[mt][nt][0]);
                uint32_t p23 = ex2_h2(acc[mt][nt][1]);
                rs01[mt] = hadd2b(rs01[mt], p01);
                rs23[mt] = hadd2b(rs23[mt], p23);
                csv[nt]  = hadd2b(csv[nt], hadd2b(p01, p23));
            }
        }

        // row sums
        #pragma unroll
        for (int mt = 0; mt < 2; mt++) {
            uint32_t u = rs01[mt], w = rs23[mt];
            u = hadd2b(u, __shfl_xor_sync(0xFFFFFFFFu, u, 1));
            u = hadd2b(u, __shfl_xor_sync(0xFFFFFFFFu, u, 2));
            w = hadd2b(w, __shfl_xor_sync(0xFFFFFFFFu, w, 1));
            w = hadd2b(w, __shfl_xor_sync(0xFFFFFFFFu, w, 2));
            if ((lane & 3) == 0) {
                int r = m0 + wm + mt * 16 + (lane >> 2);
                float2 f0 = unpack_h2(u);
                float2 f1 = unpack_h2(w);
                atomicAdd(&g_rowsum[r],     f0.x + f0.y);
                atomicAdd(&g_rowsum[r + 8], f1.x + f1.y);
            }
        }

        // col sums (off-diag only)
        if (!diag) {
            #pragma unroll
            for (int nt = 0; nt < 8; nt++) {
                uint32_t u = csv[nt];
                u = hadd2b(u, __shfl_xor_sync(0xFFFFFFFFu, u, 4));
                u = hadd2b(u, __shfl_xor_sync(0xFFFFFFFFu, u, 8));
                u = hadd2b(u, __shfl_xor_sync(0xFFFFFFFFu, u, 16));
                if (lane < 4) {
                    float2 f = unpack_h2(u);
                    int cix = n0 + wn + nt * 8 + (lane << 1);
                    atomicAdd(&g_rowsum[cix],     f.x);
                    atomicAdd(&g_rowsum[cix + 1], f.y);
                }
            }
        }

        // ---- advance pipeline ----
        if (!last) {
            if (pf) {
                CP_WAIT0();
                __syncthreads();
                cur ^= 1;
            } else {
                __syncthreads();
                load_tile_async(sb + SMEM_A, mi_n << 7, tid);
                load_tile_async(sb + SMEM_B0 + (cur << 15), ni_n << 7, tid);
                CP_COMMIT();
                CP_WAIT0();
                __syncthreads();
            }
            mi = mi_n; ni = ni_n;
        }
    }
}

// ============================================================================
// Kernel 3: finalize -> scalar loss (32 CTAs, last block writes)
// pos == dot(zn,zn)/TEMP == 2.0 exactly in nats.
// ============================================================================
__global__ void finalize_kernel(float* __restrict__ out) {
    __shared__ float red[256];
    int r = blockIdx.x * 256 + threadIdx.x;
    float S = g_rowsum[r] - ex2_approx(g_exc[r]);
    float acc = logf(S) - 2.0f;
    red[threadIdx.x] = acc;
    __syncthreads();
    #pragma unroll
    for (int s = 128; s > 0; s >>= 1) {
        if (threadIdx.x < s) red[threadIdx.x] += red[threadIdx.x + s];
        __syncthreads();
    }
    if (threadIdx.x == 0) {
        atomicAdd(&g_acc, red[0]);
        __threadfence();
        unsigned done = atomicAdd(&g_cnt, 1u);
        if (done == gridDim.x - 1) {
            float total = atomicAdd(&g_acc, 0.0f);
            out[0] = total / (float)N_TOTAL;
        }
    }
}

// ============================================================================
// launch
// ============================================================================
extern "C" void kernel_launch(void* const* d_in, const int* in_sizes, int n_in,
                              void* d_out, int out_size) {
    (void)in_sizes; (void)n_in; (void)out_size;
    const float* zi = (const float*)d_in[0];
    const float* zj = (const float*)d_in[1];
    float* out = (float*)d_out;

    normalize_kernel<<<N_TOTAL / 32, 256>>>(zi, zj);

    cudaFuncSetAttribute(gram_kernel,
                         cudaFuncAttributeMaxDynamicSharedMemorySize, SMEM_TOT);
    gram_kernel<<<GRID_GRAM, 256, SMEM_TOT>>>();

    finalize_kernel<<<N_TOTAL / 256, 256>>>(out);
}